// round 2
// baseline (speedup 1.0000x reference)
#include <cuda_runtime.h>

#define HID 256
#define ROWS 32
#define KT 32
#define THREADS 256

typedef unsigned long long u64;

// ---- packed f32x2 helpers (Blackwell FFMA2 via PTX) ----
__device__ __forceinline__ u64 pack2(float lo, float hi) {
    u64 r; asm("mov.b64 %0, {%1, %2};" : "=l"(r) : "f"(lo), "f"(hi)); return r;
}
__device__ __forceinline__ void unpack2(u64 v, float& lo, float& hi) {
    asm("mov.b64 {%0, %1}, %2;" : "=f"(lo), "=f"(hi) : "l"(v));
}
__device__ __forceinline__ u64 ffma2(u64 a, u64 b, u64 c) {
    u64 d; asm("fma.rn.f32x2 %0, %1, %2, %3;" : "=l"(d) : "l"(a), "l"(b), "l"(c)); return d;
}

// Fused PINN forward + 1st + 2nd directional derivative (along e0).
// Per-CTA: 32 samples. Activation triples (v, v1, v2) in smem, k-major [HID][ROWS].
// Two 256x256 GEMM layers, each doing 3 channels against a shared W tile.
__global__ void __launch_bounds__(THREADS, 1)
pinn_poisson_kernel(const float* __restrict__ x,
                    const float* __restrict__ W1, const float* __restrict__ b1,
                    const float* __restrict__ W2, const float* __restrict__ b2,
                    const float* __restrict__ W3, const float* __restrict__ b3,
                    const float* __restrict__ W4, const float* __restrict__ b4,
                    float* __restrict__ out, int Btot)
{
    extern __shared__ float smem[];
    float* A0 = smem;                  // value channel, [HID][ROWS]
    float* A1 = A0 + HID * ROWS;       // 1st tangent
    float* A2 = A1 + HID * ROWS;       // 2nd tangent
    float* Ws = A2 + HID * ROWS;       // W tile [KT][HID]

    const int tid  = threadIdx.x;
    const int colg = tid >> 3;         // 0..31 -> 8 output cols each
    const int rowg = tid & 7;          // 0..7  -> 4 rows each
    const int row0 = rowg * 4;
    const int col0 = colg * 8;
    const int gr0  = blockIdx.x * ROWS;

    // ---------------- Layer 1 (IN_DIM = 2, tangent = W1[0,:], curvature in = 0) ----
    {
        float x0[4], x1v[4];
        #pragma unroll
        for (int r = 0; r < 4; r++) {
            int gr = gr0 + row0 + r;
            x0[r]  = x[gr * 2 + 0];
            x1v[r] = x[gr * 2 + 1];
        }
        #pragma unroll
        for (int j = 0; j < 8; j++) {
            int c = col0 + j;
            float w0 = W1[c], w1 = W1[HID + c], bb = b1[c];
            float h[4], h1[4], h2[4];
            #pragma unroll
            for (int r = 0; r < 4; r++) {
                float z = fmaf(x0[r], w0, fmaf(x1v[r], w1, bb));
                float t = tanhf(z);
                float u = fmaf(-t, t, 1.0f);   // 1 - t^2
                h[r]  = t;
                h1[r] = u * w0;                 // (1-t^2) * z1
                h2[r] = -2.0f * t * h1[r] * w0; // -2 t (1-t^2) z1^2
            }
            *(float4*)&A0[c * ROWS + row0] = make_float4(h[0], h[1], h[2], h[3]);
            *(float4*)&A1[c * ROWS + row0] = make_float4(h1[0], h1[1], h1[2], h1[3]);
            *(float4*)&A2[c * ROWS + row0] = make_float4(h2[0], h2[1], h2[2], h2[3]);
        }
    }

    // ---------------- Layers 2 & 3: triple-channel 256x256 GEMM + tanh rules ------
    const float* Wls[2] = {W2, W3};
    const float* bls[2] = {b2, b3};

    for (int layer = 0; layer < 2; layer++) {
        const float* W = Wls[layer];
        const float* b = bls[layer];

        u64 acc0[2][8], acc1[2][8], acc2[2][8];
        #pragma unroll
        for (int j = 0; j < 8; j++) {
            float bb = b[col0 + j];
            u64 bp = pack2(bb, bb);
            acc0[0][j] = bp;  acc0[1][j] = bp;
            acc1[0][j] = 0ull; acc1[1][j] = 0ull;
            acc2[0][j] = 0ull; acc2[1][j] = 0ull;
        }

        const float4* Wg = (const float4*)W;
        float4 pre[8];
        #pragma unroll
        for (int i = 0; i < 8; i++) pre[i] = Wg[tid + i * 256];   // prefetch tile 0

        for (int t = 0; t < HID / KT; t++) {
            __syncthreads();   // prior compute/epilogue done before Ws overwrite / A reads
            #pragma unroll
            for (int i = 0; i < 8; i++) ((float4*)Ws)[tid + i * 256] = pre[i];
            __syncthreads();
            if (t + 1 < HID / KT) {
                #pragma unroll
                for (int i = 0; i < 8; i++) pre[i] = Wg[(t + 1) * 2048 + tid + i * 256];
            }
            const int kb = t * KT;
            #pragma unroll 4
            for (int kk = 0; kk < KT; kk++) {
                const int k = kb + kk;
                float4 wa = *(const float4*)&Ws[kk * HID + col0];
                float4 wb = *(const float4*)&Ws[kk * HID + col0 + 4];
                u64 w2[8];
                w2[0] = pack2(wa.x, wa.x); w2[1] = pack2(wa.y, wa.y);
                w2[2] = pack2(wa.z, wa.z); w2[3] = pack2(wa.w, wa.w);
                w2[4] = pack2(wb.x, wb.x); w2[5] = pack2(wb.y, wb.y);
                w2[6] = pack2(wb.z, wb.z); w2[7] = pack2(wb.w, wb.w);
                u64 a0p0 = *(const u64*)&A0[k * ROWS + row0];
                u64 a0p1 = *(const u64*)&A0[k * ROWS + row0 + 2];
                u64 a1p0 = *(const u64*)&A1[k * ROWS + row0];
                u64 a1p1 = *(const u64*)&A1[k * ROWS + row0 + 2];
                u64 a2p0 = *(const u64*)&A2[k * ROWS + row0];
                u64 a2p1 = *(const u64*)&A2[k * ROWS + row0 + 2];
                #pragma unroll
                for (int j = 0; j < 8; j++) {
                    acc0[0][j] = ffma2(a0p0, w2[j], acc0[0][j]);
                    acc0[1][j] = ffma2(a0p1, w2[j], acc0[1][j]);
                    acc1[0][j] = ffma2(a1p0, w2[j], acc1[0][j]);
                    acc1[1][j] = ffma2(a1p1, w2[j], acc1[1][j]);
                    acc2[0][j] = ffma2(a2p0, w2[j], acc2[0][j]);
                    acc2[1][j] = ffma2(a2p1, w2[j], acc2[1][j]);
                }
            }
        }
        __syncthreads();   // all k-reads of A done before overwriting

        // epilogue: tanh triple rule, write back to A (in place)
        #pragma unroll
        for (int j = 0; j < 8; j++) {
            int c = col0 + j;
            float av[4], t1[4], t2[4];
            unpack2(acc0[0][j], av[0], av[1]); unpack2(acc0[1][j], av[2], av[3]);
            unpack2(acc1[0][j], t1[0], t1[1]); unpack2(acc1[1][j], t1[2], t1[3]);
            unpack2(acc2[0][j], t2[0], t2[1]); unpack2(acc2[1][j], t2[2], t2[3]);
            float v[4], v1[4], v2[4];
            #pragma unroll
            for (int r = 0; r < 4; r++) {
                float tt = tanhf(av[r]);
                float u  = fmaf(-tt, tt, 1.0f);
                v[r]  = tt;
                v1[r] = u * t1[r];
                v2[r] = fmaf(u, t2[r], -2.0f * tt * v1[r] * t1[r]);
            }
            *(float4*)&A0[c * ROWS + row0] = make_float4(v[0], v[1], v[2], v[3]);
            *(float4*)&A1[c * ROWS + row0] = make_float4(v1[0], v1[1], v1[2], v1[3]);
            *(float4*)&A2[c * ROWS + row0] = make_float4(v2[0], v2[1], v2[2], v2[3]);
        }
    }
    __syncthreads();

    // ---------------- Layer 4: three dot products with W4 (+ b4 on value) --------
    {
        const int drow = tid >> 3;   // 0..31 : which sample row
        const int seg  = tid & 7;    // 0..7  : 32-wide k segment
        float s0 = 0.f, s1 = 0.f, s2 = 0.f;
        #pragma unroll 8
        for (int i = 0; i < 32; i++) {
            int k = seg * 32 + i;
            float w = W4[k];
            s0 = fmaf(A0[k * ROWS + drow], w, s0);
            s1 = fmaf(A1[k * ROWS + drow], w, s1);
            s2 = fmaf(A2[k * ROWS + drow], w, s2);
        }
        #pragma unroll
        for (int off = 4; off > 0; off >>= 1) {
            s0 += __shfl_down_sync(0xffffffffu, s0, off);
            s1 += __shfl_down_sync(0xffffffffu, s1, off);
            s2 += __shfl_down_sync(0xffffffffu, s2, off);
        }
        if (seg == 0) {
            int gr = gr0 + drow;
            out[gr]            = s0 + b4[0];
            out[Btot + gr]     = s1;
            out[2 * Btot + gr] = s2;
        }
    }
}

extern "C" void kernel_launch(void* const* d_in, const int* in_sizes, int n_in,
                              void* d_out, int out_size)
{
    const float* x  = (const float*)d_in[0];
    const float* W1 = (const float*)d_in[1];
    const float* b1 = (const float*)d_in[2];
    const float* W2 = (const float*)d_in[3];
    const float* b2 = (const float*)d_in[4];
    const float* W3 = (const float*)d_in[5];
    const float* b3 = (const float*)d_in[6];
    const float* W4 = (const float*)d_in[7];
    const float* b4 = (const float*)d_in[8];
    float* out = (float*)d_out;

    int Btot = in_sizes[0] / 2;            // x is [B, 2]
    int grid = Btot / ROWS;                // B = 131072 -> 4096 CTAs
    size_t smem = (size_t)(3 * HID * ROWS + KT * HID) * sizeof(float);  // 128 KB

    cudaFuncSetAttribute(pinn_poisson_kernel,
                         cudaFuncAttributeMaxDynamicSharedMemorySize, (int)smem);
    pinn_poisson_kernel<<<grid, THREADS, smem>>>(x, W1, b1, W2, b2, W3, b3, W4, b4,
                                                 out, Btot);
}

// round 3
// speedup vs baseline: 1.0007x; 1.0007x over previous
#include <cuda_runtime.h>

#define HID 256
#define ROWS 32
#define KT 32
#define THREADS 256

typedef unsigned long long u64;

// ---- packed f32x2 helpers (Blackwell FFMA2 via PTX) ----
__device__ __forceinline__ u64 pack2(float lo, float hi) {
    u64 r; asm("mov.b64 %0, {%1, %2};" : "=l"(r) : "f"(lo), "f"(hi)); return r;
}
__device__ __forceinline__ void unpack2(u64 v, float& lo, float& hi) {
    asm("mov.b64 {%0, %1}, %2;" : "=f"(lo), "=f"(hi) : "l"(v));
}
__device__ __forceinline__ u64 ffma2(u64 a, u64 b, u64 c) {
    u64 d; asm("fma.rn.f32x2 %0, %1, %2, %3;" : "=l"(d) : "l"(a), "l"(b), "l"(c)); return d;
}

// Fused PINN forward + 1st + 2nd directional derivative (along e0).
// Per-CTA: 32 samples. Activation triples (v, v1, v2) in smem, k-major [HID][ROWS].
// Two 256x256 GEMM layers, each doing 3 channels against a shared W tile.
__global__ void __launch_bounds__(THREADS, 1)
pinn_poisson_kernel(const float* __restrict__ x,
                    const float* __restrict__ W1, const float* __restrict__ b1,
                    const float* __restrict__ W2, const float* __restrict__ b2,
                    const float* __restrict__ W3, const float* __restrict__ b3,
                    const float* __restrict__ W4, const float* __restrict__ b4,
                    float* __restrict__ out, int Btot)
{
    extern __shared__ float smem[];
    float* A0 = smem;                  // value channel, [HID][ROWS]
    float* A1 = A0 + HID * ROWS;       // 1st tangent
    float* A2 = A1 + HID * ROWS;       // 2nd tangent
    float* Ws = A2 + HID * ROWS;       // W tile [KT][HID]

    const int tid  = threadIdx.x;
    const int colg = tid >> 3;         // 0..31 -> 8 output cols each
    const int rowg = tid & 7;          // 0..7  -> 4 rows each
    const int row0 = rowg * 4;
    const int col0 = colg * 8;
    const int gr0  = blockIdx.x * ROWS;

    // ---------------- Layer 1 (IN_DIM = 2, tangent = W1[0,:], curvature in = 0) ----
    {
        float x0[4], x1v[4];
        #pragma unroll
        for (int r = 0; r < 4; r++) {
            int gr = gr0 + row0 + r;
            x0[r]  = x[gr * 2 + 0];
            x1v[r] = x[gr * 2 + 1];
        }
        #pragma unroll
        for (int j = 0; j < 8; j++) {
            int c = col0 + j;
            float w0 = W1[c], w1 = W1[HID + c], bb = b1[c];
            float h[4], h1[4], h2[4];
            #pragma unroll
            for (int r = 0; r < 4; r++) {
                float z = fmaf(x0[r], w0, fmaf(x1v[r], w1, bb));
                float t = tanhf(z);
                float u = fmaf(-t, t, 1.0f);   // 1 - t^2
                h[r]  = t;
                h1[r] = u * w0;                 // (1-t^2) * z1
                h2[r] = -2.0f * t * h1[r] * w0; // -2 t (1-t^2) z1^2
            }
            *(float4*)&A0[c * ROWS + row0] = make_float4(h[0], h[1], h[2], h[3]);
            *(float4*)&A1[c * ROWS + row0] = make_float4(h1[0], h1[1], h1[2], h1[3]);
            *(float4*)&A2[c * ROWS + row0] = make_float4(h2[0], h2[1], h2[2], h2[3]);
        }
    }

    // ---------------- Layers 2 & 3: triple-channel 256x256 GEMM + tanh rules ------
    const float* Wls[2] = {W2, W3};
    const float* bls[2] = {b2, b3};

    for (int layer = 0; layer < 2; layer++) {
        const float* W = Wls[layer];
        const float* b = bls[layer];

        u64 acc0[2][8], acc1[2][8], acc2[2][8];
        #pragma unroll
        for (int j = 0; j < 8; j++) {
            float bb = b[col0 + j];
            u64 bp = pack2(bb, bb);
            acc0[0][j] = bp;  acc0[1][j] = bp;
            acc1[0][j] = 0ull; acc1[1][j] = 0ull;
            acc2[0][j] = 0ull; acc2[1][j] = 0ull;
        }

        const float4* Wg = (const float4*)W;
        float4 pre[8];
        #pragma unroll
        for (int i = 0; i < 8; i++) pre[i] = Wg[tid + i * 256];   // prefetch tile 0

        for (int t = 0; t < HID / KT; t++) {
            __syncthreads();   // prior compute/epilogue done before Ws overwrite / A reads
            #pragma unroll
            for (int i = 0; i < 8; i++) ((float4*)Ws)[tid + i * 256] = pre[i];
            __syncthreads();
            if (t + 1 < HID / KT) {
                #pragma unroll
                for (int i = 0; i < 8; i++) pre[i] = Wg[(t + 1) * 2048 + tid + i * 256];
            }
            const int kb = t * KT;
            #pragma unroll 4
            for (int kk = 0; kk < KT; kk++) {
                const int k = kb + kk;
                float4 wa = *(const float4*)&Ws[kk * HID + col0];
                float4 wb = *(const float4*)&Ws[kk * HID + col0 + 4];
                u64 w2[8];
                w2[0] = pack2(wa.x, wa.x); w2[1] = pack2(wa.y, wa.y);
                w2[2] = pack2(wa.z, wa.z); w2[3] = pack2(wa.w, wa.w);
                w2[4] = pack2(wb.x, wb.x); w2[5] = pack2(wb.y, wb.y);
                w2[6] = pack2(wb.z, wb.z); w2[7] = pack2(wb.w, wb.w);
                u64 a0p0 = *(const u64*)&A0[k * ROWS + row0];
                u64 a0p1 = *(const u64*)&A0[k * ROWS + row0 + 2];
                u64 a1p0 = *(const u64*)&A1[k * ROWS + row0];
                u64 a1p1 = *(const u64*)&A1[k * ROWS + row0 + 2];
                u64 a2p0 = *(const u64*)&A2[k * ROWS + row0];
                u64 a2p1 = *(const u64*)&A2[k * ROWS + row0 + 2];
                #pragma unroll
                for (int j = 0; j < 8; j++) {
                    acc0[0][j] = ffma2(a0p0, w2[j], acc0[0][j]);
                    acc0[1][j] = ffma2(a0p1, w2[j], acc0[1][j]);
                    acc1[0][j] = ffma2(a1p0, w2[j], acc1[0][j]);
                    acc1[1][j] = ffma2(a1p1, w2[j], acc1[1][j]);
                    acc2[0][j] = ffma2(a2p0, w2[j], acc2[0][j]);
                    acc2[1][j] = ffma2(a2p1, w2[j], acc2[1][j]);
                }
            }
        }
        __syncthreads();   // all k-reads of A done before overwriting

        // epilogue: tanh triple rule, write back to A (in place)
        #pragma unroll
        for (int j = 0; j < 8; j++) {
            int c = col0 + j;
            float av[4], t1[4], t2[4];
            unpack2(acc0[0][j], av[0], av[1]); unpack2(acc0[1][j], av[2], av[3]);
            unpack2(acc1[0][j], t1[0], t1[1]); unpack2(acc1[1][j], t1[2], t1[3]);
            unpack2(acc2[0][j], t2[0], t2[1]); unpack2(acc2[1][j], t2[2], t2[3]);
            float v[4], v1[4], v2[4];
            #pragma unroll
            for (int r = 0; r < 4; r++) {
                float tt = tanhf(av[r]);
                float u  = fmaf(-tt, tt, 1.0f);
                v[r]  = tt;
                v1[r] = u * t1[r];
                v2[r] = fmaf(u, t2[r], -2.0f * tt * v1[r] * t1[r]);
            }
            *(float4*)&A0[c * ROWS + row0] = make_float4(v[0], v[1], v[2], v[3]);
            *(float4*)&A1[c * ROWS + row0] = make_float4(v1[0], v1[1], v1[2], v1[3]);
            *(float4*)&A2[c * ROWS + row0] = make_float4(v2[0], v2[1], v2[2], v2[3]);
        }
    }
    __syncthreads();

    // ---------------- Layer 4: three dot products with W4 (+ b4 on value) --------
    {
        const int drow = tid >> 3;   // 0..31 : which sample row
        const int seg  = tid & 7;    // 0..7  : 32-wide k segment
        float s0 = 0.f, s1 = 0.f, s2 = 0.f;
        #pragma unroll 8
        for (int i = 0; i < 32; i++) {
            int k = seg * 32 + i;
            float w = W4[k];
            s0 = fmaf(A0[k * ROWS + drow], w, s0);
            s1 = fmaf(A1[k * ROWS + drow], w, s1);
            s2 = fmaf(A2[k * ROWS + drow], w, s2);
        }
        #pragma unroll
        for (int off = 4; off > 0; off >>= 1) {
            s0 += __shfl_down_sync(0xffffffffu, s0, off);
            s1 += __shfl_down_sync(0xffffffffu, s1, off);
            s2 += __shfl_down_sync(0xffffffffu, s2, off);
        }
        if (seg == 0) {
            int gr = gr0 + drow;
            out[gr]            = s0 + b4[0];
            out[Btot + gr]     = s1;
            out[2 * Btot + gr] = s2;
        }
    }
}

extern "C" void kernel_launch(void* const* d_in, const int* in_sizes, int n_in,
                              void* d_out, int out_size)
{
    const float* x  = (const float*)d_in[0];
    const float* W1 = (const float*)d_in[1];
    const float* b1 = (const float*)d_in[2];
    const float* W2 = (const float*)d_in[3];
    const float* b2 = (const float*)d_in[4];
    const float* W3 = (const float*)d_in[5];
    const float* b3 = (const float*)d_in[6];
    const float* W4 = (const float*)d_in[7];
    const float* b4 = (const float*)d_in[8];
    float* out = (float*)d_out;

    int Btot = in_sizes[0] / 2;            // x is [B, 2]
    int grid = Btot / ROWS;                // B = 131072 -> 4096 CTAs
    size_t smem = (size_t)(3 * HID * ROWS + KT * HID) * sizeof(float);  // 128 KB

    cudaFuncSetAttribute(pinn_poisson_kernel,
                         cudaFuncAttributeMaxDynamicSharedMemorySize, (int)smem);
    pinn_poisson_kernel<<<grid, THREADS, smem>>>(x, W1, b1, W2, b2, W3, b3, W4, b4,
                                                 out, Btot);
}

// round 5
// speedup vs baseline: 1.1928x; 1.1920x over previous
#include <cuda_runtime.h>
#include <cuda_bf16.h>
#include <cstdint>

#define HID     256
#define MROWS   32
#define THREADS 256

// ---------------- smem byte offsets ----------------
#define SM_A     0                      // 6 planes x 16KB: hi c0..2 (0..2), lo c0..2 (3..5); [kc][row][kk]
#define SM_W     (6*16384)              // 2 planes x 32KB: [n][kk] for current K-chunk
#define SM_RED   (SM_W + 2*32768)       // 3 ch x 32 rows x 4 colgroups floats
#define SM_TOTAL (SM_RED + 3*128*4)

// pre-split, pre-transposed, pre-swizzled W2/W3: [(layer*2+plane)*4+kc] tiles of 32KB
static __device__ uint4 g_Wsplit[16 * 2048];

// ---------------- helpers ----------------
__device__ __forceinline__ uint32_t s2u(const void* p) {
    uint32_t a;
    asm("{ .reg .u64 t; cvta.to.shared.u64 t, %1; cvt.u32.u64 %0, t; }" : "=r"(a) : "l"(p));
    return a;
}
__device__ __forceinline__ uint32_t sw128(uint32_t o) { return o ^ ((o >> 3) & 0x70); }

__device__ __forceinline__ uint32_t f2bf(float v, uint32_t& lo) {
    __nv_bfloat16 h = __float2bfloat16(v);
    float hv = __bfloat162float(h);
    __nv_bfloat16 l = __float2bfloat16(v - hv);
    lo = (uint32_t)__bfloat16_as_ushort(l);
    return (uint32_t)__bfloat16_as_ushort(h);
}
__device__ __forceinline__ void ldsm4(uint32_t r[4], uint32_t addr) {
    asm volatile("ldmatrix.sync.aligned.m8n8.x4.shared.b16 {%0,%1,%2,%3}, [%4];"
                 : "=r"(r[0]), "=r"(r[1]), "=r"(r[2]), "=r"(r[3]) : "r"(addr));
}
__device__ __forceinline__ void mma_bf16(float d[4], const uint32_t a[4],
                                         uint32_t b0, uint32_t b1) {
    asm volatile("mma.sync.aligned.m16n8k16.row.col.f32.bf16.bf16.f32 "
                 "{%0,%1,%2,%3}, {%4,%5,%6,%7}, {%8,%9}, {%0,%1,%2,%3};"
                 : "+f"(d[0]), "+f"(d[1]), "+f"(d[2]), "+f"(d[3])
                 : "r"(a[0]), "r"(a[1]), "r"(a[2]), "r"(a[3]), "r"(b0), "r"(b1));
}
__device__ __forceinline__ void sts32(uint32_t a, uint32_t v) {
    asm volatile("st.shared.b32 [%0], %1;" :: "r"(a), "r"(v) : "memory");
}

// ============ prep: split + transpose + swizzle W2/W3 into gmem tiles ============
__global__ void prep_kernel(const float* __restrict__ W2, const float* __restrict__ W3)
{
    int t = blockIdx.x * blockDim.x + threadIdx.x;   // 131072 threads
    int l = t >> 16;
    int r = t & 65535;
    int k = r >> 8, n = r & 255;                     // W[k][n], consecutive n coalesced
    float v = (l == 0 ? W2 : W3)[k * HID + n];
    uint32_t lo, hi = f2bf(v, lo);
    int kc = k >> 6, kk = k & 63;
    uint32_t woff = sw128((uint32_t)(n * 128 + kk * 2)) >> 1;   // u16 index within 32KB tile
    uint16_t* th = (uint16_t*)&g_Wsplit[(size_t)((l * 2 + 0) * 4 + kc) * 2048];
    uint16_t* tl = (uint16_t*)&g_Wsplit[(size_t)((l * 2 + 1) * 4 + kc) * 2048];
    th[woff] = (uint16_t)hi;
    tl[woff] = (uint16_t)lo;
}

// ============ fused PINN: layers 1-4, forward + d/dx0 + d2/dx0^2 ============
__global__ void __launch_bounds__(THREADS, 1)
pinn_tc_kernel(const float* __restrict__ x,  const float* __restrict__ W1,
               const float* __restrict__ b1, const float* __restrict__ b2,
               const float* __restrict__ b3, const float* __restrict__ W4,
               const float* __restrict__ b4, float* __restrict__ out, int Btot)
{
    extern __shared__ char smem[];
    uint32_t sb = s2u(smem);
    const int tid = threadIdx.x, lane = tid & 31, w = tid >> 5;
    const int gr0 = blockIdx.x * MROWS;

    // ---------------- layer 1: closed-form triple -> A planes ----------------
    {
        const int row  = tid >> 3;
        const int fseg = tid & 7;
        const float x0 = x[(gr0 + row) * 2 + 0];
        const float x1 = x[(gr0 + row) * 2 + 1];
        const int f0 = fseg * 32;
        const int kc = f0 >> 6;
        const uint32_t rowoff = sw128((uint32_t)(row * 128));
        #pragma unroll
        for (int i = 0; i < 32; i += 2) {
            uint32_t pk[6] = {0, 0, 0, 0, 0, 0};
            #pragma unroll
            for (int j = 0; j < 2; j++) {
                int f = f0 + i + j;
                float w0 = W1[f], w1 = W1[HID + f];
                float z = fmaf(x0, w0, fmaf(x1, w1, b1[f]));
                float th = tanhf(z);
                float u  = fmaf(-th, th, 1.0f);
                float v0 = th, v1 = u * w0, v2 = -2.0f * th * v1 * w0;
                uint32_t lo, hi;
                hi = f2bf(v0, lo); pk[0] |= hi << (16 * j); pk[3] |= lo << (16 * j);
                hi = f2bf(v1, lo); pk[1] |= hi << (16 * j); pk[4] |= lo << (16 * j);
                hi = f2bf(v2, lo); pk[2] |= hi << (16 * j); pk[5] |= lo << (16 * j);
            }
            uint32_t off = sb + SM_A + kc * 4096 + (rowoff ^ (uint32_t)(((f0 + i) & 63) * 2));
            #pragma unroll
            for (int p = 0; p < 6; p++) sts32(off + p * 16384, pk[p]);
        }
    }
    __syncthreads();

    // ---------------- warp tiling constants ----------------
    const int rowg = w & 1;            // rows rowg*16 .. +15
    const int cp   = w >> 1;           // col groups: cp*64 and cp*64+32
    const uint32_t m     = (uint32_t)(lane >> 3);
    const uint32_t rselA = (m & 1) * 8 + (lane & 7);
    const uint32_t kofA  = (uint32_t)(lane >> 4) * 8;
    const uint32_t aBase = sw128((uint32_t)((rowg * 16 + rselA) * 128));
    const uint32_t nselB = (uint32_t)(lane >> 4) * 8 + (lane & 7);
    const uint32_t kofB  = (m & 1) * 8;
    uint32_t bBase[2][2];
    #pragma unroll
    for (int r = 0; r < 2; r++)
        #pragma unroll
        for (int nf16 = 0; nf16 < 2; nf16++)
            bBase[r][nf16] = sw128((uint32_t)((cp * 64 + r * 32 + nf16 * 16 + nselB) * 128));

    const int r0 = rowg * 16 + (lane >> 2);
    float s4[2][3] = {{0.f, 0.f, 0.f}, {0.f, 0.f, 0.f}};   // layer-4 partials [rowhalf][ch]

    for (int layer = 0; layer < 2; layer++) {
        float acc[2][3][4][4];
        #pragma unroll
        for (int r = 0; r < 2; r++)
            #pragma unroll
            for (int c = 0; c < 3; c++)
                #pragma unroll
                for (int nf = 0; nf < 4; nf++)
                    #pragma unroll
                    for (int q = 0; q < 4; q++) acc[r][c][nf][q] = 0.f;

        for (int kc = 0; kc < 4; kc++) {
            // ---- stage W chunk: 2 planes x 32KB, straight uint4 copy ----
            {
                const uint4* s0 = &g_Wsplit[(size_t)((layer * 2 + 0) * 4 + kc) * 2048];
                const uint4* s1 = &g_Wsplit[(size_t)((layer * 2 + 1) * 4 + kc) * 2048];
                uint4* d0 = (uint4*)(smem + SM_W);
                uint4* d1 = (uint4*)(smem + SM_W + 32768);
                #pragma unroll
                for (int i = 0; i < 8; i++) {
                    d0[tid + i * 256] = s0[tid + i * 256];
                    d1[tid + i * 256] = s1[tid + i * 256];
                }
            }
            __syncthreads();
            // ---- mma over 4 K=16 steps ----
            #pragma unroll
            for (int ks = 0; ks < 4; ks++) {
                const uint32_t kxA = (uint32_t)((ks * 16 + kofA) * 2);
                const uint32_t kxB = (uint32_t)((ks * 16 + kofB) * 2);
                uint32_t ah[3][4], al[3][4];
                const uint32_t abase = sb + SM_A + kc * 4096 + (aBase ^ kxA);
                #pragma unroll
                for (int c = 0; c < 3; c++) {
                    ldsm4(ah[c], abase + c * 16384);
                    ldsm4(al[c], abase + (3 + c) * 16384);
                }
                #pragma unroll
                for (int r = 0; r < 2; r++)
                    #pragma unroll
                    for (int nf16 = 0; nf16 < 2; nf16++) {
                        const uint32_t baddr = sb + SM_W + (bBase[r][nf16] ^ kxB);
                        uint32_t bh[4], bl[4];
                        ldsm4(bh, baddr);
                        ldsm4(bl, baddr + 32768);
                        #pragma unroll
                        for (int c = 0; c < 3; c++) {
                            mma_bf16(acc[r][c][nf16 * 2],     ah[c], bh[0], bh[1]);
                            mma_bf16(acc[r][c][nf16 * 2],     al[c], bh[0], bh[1]);
                            mma_bf16(acc[r][c][nf16 * 2],     ah[c], bl[0], bl[1]);
                            mma_bf16(acc[r][c][nf16 * 2 + 1], ah[c], bh[2], bh[3]);
                            mma_bf16(acc[r][c][nf16 * 2 + 1], al[c], bh[2], bh[3]);
                            mma_bf16(acc[r][c][nf16 * 2 + 1], ah[c], bl[2], bl[3]);
                        }
                    }
            }
            __syncthreads();   // W chunk fully consumed before next overwrite
        }

        // ---------------- epilogue ----------------
        if (layer == 0) {
            // tanh triple rule -> write next A planes (in place; all reads done)
            #pragma unroll
            for (int r = 0; r < 2; r++) {
                int colb = cp * 64 + r * 32;
                #pragma unroll
                for (int nf = 0; nf < 4; nf++) {
                    int col = colb + nf * 8 + (lane & 3) * 2;
                    #pragma unroll
                    for (int half = 0; half < 2; half++) {
                        int row = r0 + half * 8;
                        uint32_t pk[6] = {0, 0, 0, 0, 0, 0};
                        #pragma unroll
                        for (int j = 0; j < 2; j++) {
                            float z  = acc[r][0][nf][half * 2 + j] + __ldg(&b2[col + j]);
                            float z1 = acc[r][1][nf][half * 2 + j];
                            float z2 = acc[r][2][nf][half * 2 + j];
                            float th = tanhf(z);
                            float u  = fmaf(-th, th, 1.0f);
                            float v0 = th, v1 = u * z1;
                            float v2 = fmaf(u, z2, -2.0f * th * v1 * z1);
                            uint32_t lo, hi;
                            hi = f2bf(v0, lo); pk[0] |= hi << (16 * j); pk[3] |= lo << (16 * j);
                            hi = f2bf(v1, lo); pk[1] |= hi << (16 * j); pk[4] |= lo << (16 * j);
                            hi = f2bf(v2, lo); pk[2] |= hi << (16 * j); pk[5] |= lo << (16 * j);
                        }
                        uint32_t off = sb + SM_A + (col >> 6) * 4096 +
                                       sw128((uint32_t)(row * 128 + (col & 63) * 2));
                        #pragma unroll
                        for (int p = 0; p < 6; p++) sts32(off + p * 16384, pk[p]);
                    }
                }
            }
        } else {
            // tanh triple rule fused with layer-4 dot products (W4)
            #pragma unroll
            for (int r = 0; r < 2; r++) {
                int colb = cp * 64 + r * 32;
                #pragma unroll
                for (int nf = 0; nf < 4; nf++) {
                    int col = colb + nf * 8 + (lane & 3) * 2;
                    #pragma unroll
                    for (int half = 0; half < 2; half++) {
                        #pragma unroll
                        for (int j = 0; j < 2; j++) {
                            float z  = acc[r][0][nf][half * 2 + j] + __ldg(&b3[col + j]);
                            float z1 = acc[r][1][nf][half * 2 + j];
                            float z2 = acc[r][2][nf][half * 2 + j];
                            float th = tanhf(z);
                            float u  = fmaf(-th, th, 1.0f);
                            float v0 = th, v1 = u * z1;
                            float v2 = fmaf(u, z2, -2.0f * th * v1 * z1);
                            float w4v = __ldg(&W4[col + j]);
                            s4[half][0] = fmaf(v0, w4v, s4[half][0]);
                            s4[half][1] = fmaf(v1, w4v, s4[half][1]);
                            s4[half][2] = fmaf(v2, w4v, s4[half][2]);
                        }
                    }
                }
            }
        }
    }

    // ---------------- layer-4 reduction ----------------
    #pragma unroll
    for (int half = 0; half < 2; half++)
        #pragma unroll
        for (int c = 0; c < 3; c++) {
            float v = s4[half][c];
            v += __shfl_xor_sync(0xffffffffu, v, 1);
            v += __shfl_xor_sync(0xffffffffu, v, 2);
            s4[half][c] = v;
        }
    float* red = (float*)(smem + SM_RED);
    if ((lane & 3) == 0) {
        int q  = lane >> 2;
        int ra = rowg * 16 + q, rb = ra + 8;
        #pragma unroll
        for (int c = 0; c < 3; c++) {
            red[c * 128 + ra * 4 + cp] = s4[0][c];
            red[c * 128 + rb * 4 + cp] = s4[1][c];
        }
    }
    __syncthreads();
    if (tid < 96) {
        int ch = tid >> 5, row = tid & 31;
        float s = red[ch * 128 + row * 4 + 0] + red[ch * 128 + row * 4 + 1] +
                  red[ch * 128 + row * 4 + 2] + red[ch * 128 + row * 4 + 3];
        if (ch == 0) s += b4[0];
        out[ch * Btot + gr0 + row] = s;
    }
}

extern "C" void kernel_launch(void* const* d_in, const int* in_sizes, int n_in,
                              void* d_out, int out_size)
{
    const float* x  = (const float*)d_in[0];
    const float* W1 = (const float*)d_in[1];
    const float* b1 = (const float*)d_in[2];
    const float* W2 = (const float*)d_in[3];
    const float* b2 = (const float*)d_in[4];
    const float* W3 = (const float*)d_in[5];
    const float* b3 = (const float*)d_in[6];
    const float* W4 = (const float*)d_in[7];
    const float* b4 = (const float*)d_in[8];
    float* out = (float*)d_out;

    int Btot = in_sizes[0] / 2;          // 131072
    int grid = Btot / MROWS;             // 4096 CTAs

    cudaFuncSetAttribute(pinn_tc_kernel,
                         cudaFuncAttributeMaxDynamicSharedMemorySize, SM_TOTAL);

    prep_kernel<<<512, 256>>>(W2, W3);
    pinn_tc_kernel<<<grid, THREADS, SM_TOTAL>>>(x, W1, b1, b2, b3, W4, b4, out, Btot);
}

// round 6
// speedup vs baseline: 2.7485x; 2.3041x over previous
#include <cuda_runtime.h>
#include <cuda_fp16.h>
#include <cstdint>

#define HID     256
#define MROWS   32
#define THREADS 256

// ---------------- smem byte offsets ----------------
#define SM_A     0                       // 6 planes x 16KB fp16: hi c0..2, lo c0..2 ; [kc][row][kk]
#define SM_W     (6*16384)               // 2 x 32KB double-buffered W chunk: [n 256][kk 64] fp16
#define SM_RED   (SM_W + 2*32768)        // 3ch x 32 rows x 4 colgroups floats
#define SM_TOTAL (SM_RED + 3*128*4)

// pre-rounded fp16, transposed, swizzled W2/W3: [layer*4+kc] tiles of 32KB
static __device__ uint4 g_Wsplit[8 * 2048];

// ---------------- helpers ----------------
__device__ __forceinline__ uint32_t s2u(const void* p) {
    uint32_t a;
    asm("{ .reg .u64 t; cvta.to.shared.u64 t, %1; cvt.u32.u64 %0, t; }" : "=r"(a) : "l"(p));
    return a;
}
__device__ __forceinline__ uint32_t sw128(uint32_t o) { return o ^ ((o >> 3) & 0x70); }

// float -> (fp16 hi, fp16 lo residual)
__device__ __forceinline__ uint32_t f2h(float v, uint32_t& lo) {
    __half h = __float2half_rn(v);
    float hv = __half2float(h);
    __half l = __float2half_rn(v - hv);
    lo = (uint32_t)__half_as_ushort(l);
    return (uint32_t)__half_as_ushort(h);
}
__device__ __forceinline__ void ldsm4(uint32_t r[4], uint32_t addr) {
    asm volatile("ldmatrix.sync.aligned.m8n8.x4.shared.b16 {%0,%1,%2,%3}, [%4];"
                 : "=r"(r[0]), "=r"(r[1]), "=r"(r[2]), "=r"(r[3]) : "r"(addr));
}
__device__ __forceinline__ void mma_fp16(float d[4], const uint32_t a[4],
                                         uint32_t b0, uint32_t b1) {
    asm volatile("mma.sync.aligned.m16n8k16.row.col.f32.f16.f16.f32 "
                 "{%0,%1,%2,%3}, {%4,%5,%6,%7}, {%8,%9}, {%0,%1,%2,%3};"
                 : "+f"(d[0]), "+f"(d[1]), "+f"(d[2]), "+f"(d[3])
                 : "r"(a[0]), "r"(a[1]), "r"(a[2]), "r"(a[3]), "r"(b0), "r"(b1));
}
__device__ __forceinline__ void sts32(uint32_t a, uint32_t v) {
    asm volatile("st.shared.b32 [%0], %1;" :: "r"(a), "r"(v) : "memory");
}
__device__ __forceinline__ void cpasync16(uint32_t dst, const void* src) {
    asm volatile("cp.async.cg.shared.global [%0], [%1], 16;" :: "r"(dst), "l"(src));
}

// ============ prep: round to fp16 + transpose + swizzle W2/W3 ============
__global__ void prep_kernel(const float* __restrict__ W2, const float* __restrict__ W3)
{
    int t = blockIdx.x * blockDim.x + threadIdx.x;   // 131072 threads
    int l = t >> 16;
    int r = t & 65535;
    int k = r >> 8, n = r & 255;                     // W[k][n]
    float v = (l == 0 ? W2 : W3)[k * HID + n];
    __half h = __float2half_rn(v);
    int kc = k >> 6, kk = k & 63;
    uint32_t woff = sw128((uint32_t)(n * 128 + kk * 2)) >> 1;
    uint16_t* th = (uint16_t*)&g_Wsplit[(size_t)(l * 4 + kc) * 2048];
    th[woff] = (uint16_t)__half_as_ushort(h);
}

// ============ fused PINN: layers 1-4, forward + d/dx0 + d2/dx0^2 ============
__global__ void __launch_bounds__(THREADS, 1)
pinn_tc_kernel(const float* __restrict__ x,  const float* __restrict__ W1,
               const float* __restrict__ b1, const float* __restrict__ b2,
               const float* __restrict__ b3, const float* __restrict__ W4,
               const float* __restrict__ b4, float* __restrict__ out, int Btot)
{
    extern __shared__ char smem[];
    uint32_t sb = s2u(smem);
    const int tid = threadIdx.x, lane = tid & 31, w = tid >> 5;
    const int gr0 = blockIdx.x * MROWS;

    // ---------------- layer 1: closed-form triple -> A planes (fp16 hi/lo) ------
    {
        const int row  = tid >> 3;
        const int fseg = tid & 7;
        const float x0 = x[(gr0 + row) * 2 + 0];
        const float x1 = x[(gr0 + row) * 2 + 1];
        const int f0 = fseg * 32;
        const int kc = f0 >> 6;
        const uint32_t rowoff = sw128((uint32_t)(row * 128));
        #pragma unroll
        for (int i = 0; i < 32; i += 2) {
            uint32_t pk[6] = {0, 0, 0, 0, 0, 0};
            #pragma unroll
            for (int j = 0; j < 2; j++) {
                int f = f0 + i + j;
                float w0 = W1[f], w1 = W1[HID + f];
                float z = fmaf(x0, w0, fmaf(x1, w1, b1[f]));
                float th = tanhf(z);
                float u  = fmaf(-th, th, 1.0f);
                float v0 = th, v1 = u * w0, v2 = -2.0f * th * v1 * w0;
                uint32_t lo, hi;
                hi = f2h(v0, lo); pk[0] |= hi << (16 * j); pk[3] |= lo << (16 * j);
                hi = f2h(v1, lo); pk[1] |= hi << (16 * j); pk[4] |= lo << (16 * j);
                hi = f2h(v2, lo); pk[2] |= hi << (16 * j); pk[5] |= lo << (16 * j);
            }
            uint32_t off = sb + SM_A + kc * 4096 + (rowoff ^ (uint32_t)(((f0 + i) & 63) * 2));
            #pragma unroll
            for (int p = 0; p < 6; p++) sts32(off + p * 16384, pk[p]);
        }
    }

    // ---------------- warp tiling constants ----------------
    const int rowg = w & 1;
    const int cp   = w >> 1;
    const uint32_t m     = (uint32_t)(lane >> 3);
    const uint32_t rselA = (m & 1) * 8 + (lane & 7);
    const uint32_t kofA  = (uint32_t)(lane >> 4) * 8;
    const uint32_t aBase = sw128((uint32_t)((rowg * 16 + rselA) * 128));
    const uint32_t nselB = (uint32_t)(lane >> 4) * 8 + (lane & 7);
    const uint32_t kofB  = (m & 1) * 8;
    uint32_t bBase[2][2];
    #pragma unroll
    for (int r = 0; r < 2; r++)
        #pragma unroll
        for (int nf16 = 0; nf16 < 2; nf16++)
            bBase[r][nf16] = sw128((uint32_t)((cp * 64 + r * 32 + nf16 * 16 + nselB) * 128));

    const int r0 = rowg * 16 + (lane >> 2);
    float s4[2][3] = {{0.f, 0.f, 0.f}, {0.f, 0.f, 0.f}};

    // ---- prologue: async-prefetch chunk 0 (layer 0, kc 0) ----
    {
        const uint4* src = &g_Wsplit[0];
        uint32_t dst = sb + SM_W + (uint32_t)tid * 16;
        #pragma unroll
        for (int i = 0; i < 8; i++) cpasync16(dst + i * 4096, src + tid + i * 256);
        asm volatile("cp.async.commit_group;" ::: "memory");
    }

    for (int layer = 0; layer < 2; layer++) {
        float acc[2][3][4][4];
        #pragma unroll
        for (int r = 0; r < 2; r++)
            #pragma unroll
            for (int c = 0; c < 3; c++)
                #pragma unroll
                for (int nf = 0; nf < 4; nf++)
                    #pragma unroll
                    for (int q = 0; q < 4; q++) acc[r][c][nf][q] = 0.f;

        for (int kc = 0; kc < 4; kc++) {
            const int t = layer * 4 + kc;
            __syncthreads();             // prior reads of buf[(t+1)&1] done; layer-1 A stores done
            if (t < 7) {                 // prefetch next chunk into other buffer
                const uint4* src = &g_Wsplit[(size_t)(t + 1) * 2048];
                uint32_t dst = sb + SM_W + (uint32_t)((t + 1) & 1) * 32768 + (uint32_t)tid * 16;
                #pragma unroll
                for (int i = 0; i < 8; i++) cpasync16(dst + i * 4096, src + tid + i * 256);
                asm volatile("cp.async.commit_group;" ::: "memory");
                asm volatile("cp.async.wait_group 1;" ::: "memory");
            } else {
                asm volatile("cp.async.wait_group 0;" ::: "memory");
            }
            __syncthreads();             // chunk t visible to all warps

            const uint32_t wbase = sb + SM_W + (uint32_t)(t & 1) * 32768;
            #pragma unroll
            for (int ks = 0; ks < 4; ks++) {
                const uint32_t kxA = (uint32_t)((ks * 16 + kofA) * 2);
                const uint32_t kxB = (uint32_t)((ks * 16 + kofB) * 2);
                uint32_t ah[3][4], al[3][4];
                const uint32_t abase = sb + SM_A + kc * 4096 + (aBase ^ kxA);
                #pragma unroll
                for (int c = 0; c < 3; c++) {
                    ldsm4(ah[c], abase + c * 16384);
                    ldsm4(al[c], abase + (3 + c) * 16384);
                }
                #pragma unroll
                for (int r = 0; r < 2; r++)
                    #pragma unroll
                    for (int nf16 = 0; nf16 < 2; nf16++) {
                        uint32_t bh[4];
                        ldsm4(bh, wbase + (bBase[r][nf16] ^ kxB));
                        #pragma unroll
                        for (int c = 0; c < 3; c++) {
                            mma_fp16(acc[r][c][nf16 * 2],     ah[c], bh[0], bh[1]);
                            mma_fp16(acc[r][c][nf16 * 2],     al[c], bh[0], bh[1]);
                            mma_fp16(acc[r][c][nf16 * 2 + 1], ah[c], bh[2], bh[3]);
                            mma_fp16(acc[r][c][nf16 * 2 + 1], al[c], bh[2], bh[3]);
                        }
                    }
            }
        }
        __syncthreads();    // all A reads done before epilogue overwrites A

        if (layer == 0) {
            // tanh triple rule -> write next A planes (fp16 hi/lo, in place)
            #pragma unroll
            for (int r = 0; r < 2; r++) {
                int colb = cp * 64 + r * 32;
                #pragma unroll
                for (int nf = 0; nf < 4; nf++) {
                    int col = colb + nf * 8 + (lane & 3) * 2;
                    #pragma unroll
                    for (int half = 0; half < 2; half++) {
                        int row = r0 + half * 8;
                        uint32_t pk[6] = {0, 0, 0, 0, 0, 0};
                        #pragma unroll
                        for (int j = 0; j < 2; j++) {
                            float z  = acc[r][0][nf][half * 2 + j] + __ldg(&b2[col + j]);
                            float z1 = acc[r][1][nf][half * 2 + j];
                            float z2 = acc[r][2][nf][half * 2 + j];
                            float th = tanhf(z);
                            float u  = fmaf(-th, th, 1.0f);
                            float v0 = th, v1 = u * z1;
                            float v2 = fmaf(u, z2, -2.0f * th * v1 * z1);
                            uint32_t lo, hi;
                            hi = f2h(v0, lo); pk[0] |= hi << (16 * j); pk[3] |= lo << (16 * j);
                            hi = f2h(v1, lo); pk[1] |= hi << (16 * j); pk[4] |= lo << (16 * j);
                            hi = f2h(v2, lo); pk[2] |= hi << (16 * j); pk[5] |= lo << (16 * j);
                        }
                        uint32_t off = sb + SM_A + (col >> 6) * 4096 +
                                       sw128((uint32_t)(row * 128 + (col & 63) * 2));
                        #pragma unroll
                        for (int p = 0; p < 6; p++) sts32(off + p * 16384, pk[p]);
                    }
                }
            }
        } else {
            // tanh triple rule fused with layer-4 dot products (W4)
            #pragma unroll
            for (int r = 0; r < 2; r++) {
                int colb = cp * 64 + r * 32;
                #pragma unroll
                for (int nf = 0; nf < 4; nf++) {
                    int col = colb + nf * 8 + (lane & 3) * 2;
                    #pragma unroll
                    for (int half = 0; half < 2; half++) {
                        #pragma unroll
                        for (int j = 0; j < 2; j++) {
                            float z  = acc[r][0][nf][half * 2 + j] + __ldg(&b3[col + j]);
                            float z1 = acc[r][1][nf][half * 2 + j];
                            float z2 = acc[r][2][nf][half * 2 + j];
                            float th = tanhf(z);
                            float u  = fmaf(-th, th, 1.0f);
                            float v0 = th, v1 = u * z1;
                            float v2 = fmaf(u, z2, -2.0f * th * v1 * z1);
                            float w4v = __ldg(&W4[col + j]);
                            s4[half][0] = fmaf(v0, w4v, s4[half][0]);
                            s4[half][1] = fmaf(v1, w4v, s4[half][1]);
                            s4[half][2] = fmaf(v2, w4v, s4[half][2]);
                        }
                    }
                }
            }
        }
    }

    // ---------------- layer-4 reduction ----------------
    #pragma unroll
    for (int half = 0; half < 2; half++)
        #pragma unroll
        for (int c = 0; c < 3; c++) {
            float v = s4[half][c];
            v += __shfl_xor_sync(0xffffffffu, v, 1);
            v += __shfl_xor_sync(0xffffffffu, v, 2);
            s4[half][c] = v;
        }
    float* red = (float*)(smem + SM_RED);
    if ((lane & 3) == 0) {
        int q  = lane >> 2;
        int ra = rowg * 16 + q, rb = ra + 8;
        #pragma unroll
        for (int c = 0; c < 3; c++) {
            red[c * 128 + ra * 4 + cp] = s4[0][c];
            red[c * 128 + rb * 4 + cp] = s4[1][c];
        }
    }
    __syncthreads();
    if (tid < 96) {
        int ch = tid >> 5, row = tid & 31;
        float s = red[ch * 128 + row * 4 + 0] + red[ch * 128 + row * 4 + 1] +
                  red[ch * 128 + row * 4 + 2] + red[ch * 128 + row * 4 + 3];
        if (ch == 0) s += b4[0];
        out[ch * Btot + gr0 + row] = s;
    }
}

extern "C" void kernel_launch(void* const* d_in, const int* in_sizes, int n_in,
                              void* d_out, int out_size)
{
    const float* x  = (const float*)d_in[0];
    const float* W1 = (const float*)d_in[1];
    const float* b1 = (const float*)d_in[2];
    const float* W2 = (const float*)d_in[3];
    const float* b2 = (const float*)d_in[4];
    const float* W3 = (const float*)d_in[5];
    const float* b3 = (const float*)d_in[6];
    const float* W4 = (const float*)d_in[7];
    const float* b4 = (const float*)d_in[8];
    float* out = (float*)d_out;

    int Btot = in_sizes[0] / 2;          // 131072
    int grid = Btot / MROWS;             // 4096 CTAs

    cudaFuncSetAttribute(pinn_tc_kernel,
                         cudaFuncAttributeMaxDynamicSharedMemorySize, SM_TOTAL);

    prep_kernel<<<512, 256>>>(W2, W3);
    pinn_tc_kernel<<<grid, THREADS, SM_TOTAL>>>(x, W1, b1, b2, b3, W4, b4, out, Btot);
}

// round 7
// speedup vs baseline: 3.2065x; 1.1666x over previous
#include <cuda_runtime.h>
#include <cuda_fp16.h>
#include <cstdint>

#define HID     256
#define MROWS   16
#define THREADS 128

// ---------------- smem byte offsets ----------------
// A: 6 planes x 8KB fp16 (hi c0..2, lo c0..2); each plane [kc 4][row 16][kk 64]
#define SM_A     0
#define SM_W     (6*8192)                // 2 x 32KB double-buffered W chunk [n 256][kk 64] fp16
#define SM_RED   (SM_W + 2*32768)        // 3ch x 16 rows x 4 colgroups floats
#define SM_TOTAL (SM_RED + 3*64*4)       // 115,200 B -> 2 CTAs/SM

// pre-rounded fp16, transposed, swizzled W2/W3: [layer*4+kc] tiles of 32KB
static __device__ uint4 g_Wsplit[8 * 2048];

// ---------------- helpers ----------------
__device__ __forceinline__ uint32_t s2u(const void* p) {
    uint32_t a;
    asm("{ .reg .u64 t; cvta.to.shared.u64 t, %1; cvt.u32.u64 %0, t; }" : "=r"(a) : "l"(p));
    return a;
}
__device__ __forceinline__ uint32_t sw128(uint32_t o) { return o ^ ((o >> 3) & 0x70); }

// float -> (fp16 hi, fp16 lo residual)
__device__ __forceinline__ uint32_t f2h(float v, uint32_t& lo) {
    __half h = __float2half_rn(v);
    float hv = __half2float(h);
    __half l = __float2half_rn(v - hv);
    lo = (uint32_t)__half_as_ushort(l);
    return (uint32_t)__half_as_ushort(h);
}
__device__ __forceinline__ void ldsm4(uint32_t r[4], uint32_t addr) {
    asm volatile("ldmatrix.sync.aligned.m8n8.x4.shared.b16 {%0,%1,%2,%3}, [%4];"
                 : "=r"(r[0]), "=r"(r[1]), "=r"(r[2]), "=r"(r[3]) : "r"(addr));
}
__device__ __forceinline__ void mma_fp16(float d[4], const uint32_t a[4],
                                         uint32_t b0, uint32_t b1) {
    asm volatile("mma.sync.aligned.m16n8k16.row.col.f32.f16.f16.f32 "
                 "{%0,%1,%2,%3}, {%4,%5,%6,%7}, {%8,%9}, {%0,%1,%2,%3};"
                 : "+f"(d[0]), "+f"(d[1]), "+f"(d[2]), "+f"(d[3])
                 : "r"(a[0]), "r"(a[1]), "r"(a[2]), "r"(a[3]), "r"(b0), "r"(b1));
}
__device__ __forceinline__ void sts32(uint32_t a, uint32_t v) {
    asm volatile("st.shared.b32 [%0], %1;" :: "r"(a), "r"(v) : "memory");
}
__device__ __forceinline__ void cpasync16(uint32_t dst, const void* src) {
    asm volatile("cp.async.cg.shared.global [%0], [%1], 16;" :: "r"(dst), "l"(src));
}

// ============ prep: round to fp16 + transpose + swizzle W2/W3 ============
__global__ void prep_kernel(const float* __restrict__ W2, const float* __restrict__ W3)
{
    int t = blockIdx.x * blockDim.x + threadIdx.x;   // 131072 threads
    int l = t >> 16;
    int r = t & 65535;
    int k = r >> 8, n = r & 255;                     // W[k][n]
    float v = (l == 0 ? W2 : W3)[k * HID + n];
    __half h = __float2half_rn(v);
    int kc = k >> 6, kk = k & 63;
    uint32_t woff = sw128((uint32_t)(n * 128 + kk * 2)) >> 1;
    uint16_t* th = (uint16_t*)&g_Wsplit[(size_t)(l * 4 + kc) * 2048];
    th[woff] = (uint16_t)__half_as_ushort(h);
}

// ============ fused PINN: layers 1-4, forward + d/dx0 + d2/dx0^2 ============
__global__ void __launch_bounds__(THREADS, 2)
pinn_tc_kernel(const float* __restrict__ x,  const float* __restrict__ W1,
               const float* __restrict__ b1, const float* __restrict__ b2,
               const float* __restrict__ b3, const float* __restrict__ W4,
               const float* __restrict__ b4, float* __restrict__ out, int Btot)
{
    extern __shared__ char smem[];
    uint32_t sb = s2u(smem);
    const int tid = threadIdx.x, lane = tid & 31, w = tid >> 5;
    const int gr0 = blockIdx.x * MROWS;

    // ---------------- layer 1: closed-form triple -> A planes (fp16 hi/lo) ------
    {
        const int row  = tid >> 3;           // 0..15
        const int fseg = tid & 7;
        const float x0 = x[(gr0 + row) * 2 + 0];
        const float x1 = x[(gr0 + row) * 2 + 1];
        const int f0 = fseg * 32;
        const int kc = f0 >> 6;
        const uint32_t rowoff = sw128((uint32_t)(row * 128));
        #pragma unroll
        for (int i = 0; i < 32; i += 2) {
            uint32_t pk[6] = {0, 0, 0, 0, 0, 0};
            #pragma unroll
            for (int j = 0; j < 2; j++) {
                int f = f0 + i + j;
                float w0 = W1[f], w1 = W1[HID + f];
                float z = fmaf(x0, w0, fmaf(x1, w1, b1[f]));
                float th = tanhf(z);
                float u  = fmaf(-th, th, 1.0f);
                float v0 = th, v1 = u * w0, v2 = -2.0f * th * v1 * w0;
                uint32_t lo, hi;
                hi = f2h(v0, lo); pk[0] |= hi << (16 * j); pk[3] |= lo << (16 * j);
                hi = f2h(v1, lo); pk[1] |= hi << (16 * j); pk[4] |= lo << (16 * j);
                hi = f2h(v2, lo); pk[2] |= hi << (16 * j); pk[5] |= lo << (16 * j);
            }
            uint32_t off = sb + SM_A + kc * 2048 + (rowoff ^ (uint32_t)(((f0 + i) & 63) * 2));
            #pragma unroll
            for (int p = 0; p < 6; p++) sts32(off + p * 8192, pk[p]);
        }
    }

    // ---------------- warp tiling constants (4 warps, M=16, each warp 64 N-cols) ----
    const int cp = w;                        // col groups: cp*64 .. +63
    const uint32_t m     = (uint32_t)(lane >> 3);
    const uint32_t rselA = (m & 1) * 8 + (lane & 7);     // 0..15
    const uint32_t kofA  = (uint32_t)(lane >> 4) * 8;
    const uint32_t aBase = sw128((uint32_t)(rselA * 128));
    const uint32_t nselB = (uint32_t)(lane >> 4) * 8 + (lane & 7);
    const uint32_t kofB  = (m & 1) * 8;
    uint32_t bBase[2][2];
    #pragma unroll
    for (int r = 0; r < 2; r++)
        #pragma unroll
        for (int nf16 = 0; nf16 < 2; nf16++)
            bBase[r][nf16] = sw128((uint32_t)((cp * 64 + r * 32 + nf16 * 16 + nselB) * 128));

    const int r0 = lane >> 2;                // 0..7
    float s4[2][3] = {{0.f, 0.f, 0.f}, {0.f, 0.f, 0.f}};

    // ---- prologue: async-prefetch chunk 0 ----
    {
        const uint4* src = &g_Wsplit[0];
        uint32_t dst = sb + SM_W + (uint32_t)tid * 16;
        #pragma unroll
        for (int i = 0; i < 16; i++) cpasync16(dst + i * 2048, src + tid + i * 128);
        asm volatile("cp.async.commit_group;" ::: "memory");
    }

    for (int layer = 0; layer < 2; layer++) {
        float acc[2][3][4][4];
        #pragma unroll
        for (int r = 0; r < 2; r++)
            #pragma unroll
            for (int c = 0; c < 3; c++)
                #pragma unroll
                for (int nf = 0; nf < 4; nf++)
                    #pragma unroll
                    for (int q = 0; q < 4; q++) acc[r][c][nf][q] = 0.f;

        for (int kc = 0; kc < 4; kc++) {
            const int t = layer * 4 + kc;
            __syncthreads();             // prior reads of buf[(t+1)&1] done; layer-1 A stores done
            if (t < 7) {                 // prefetch next chunk into other buffer
                const uint4* src = &g_Wsplit[(size_t)(t + 1) * 2048];
                uint32_t dst = sb + SM_W + (uint32_t)((t + 1) & 1) * 32768 + (uint32_t)tid * 16;
                #pragma unroll
                for (int i = 0; i < 16; i++) cpasync16(dst + i * 2048, src + tid + i * 128);
                asm volatile("cp.async.commit_group;" ::: "memory");
                asm volatile("cp.async.wait_group 1;" ::: "memory");
            } else {
                asm volatile("cp.async.wait_group 0;" ::: "memory");
            }
            __syncthreads();             // chunk t visible to all warps

            const uint32_t wbase = sb + SM_W + (uint32_t)(t & 1) * 32768;
            #pragma unroll
            for (int ks = 0; ks < 4; ks++) {
                const uint32_t kxA = (uint32_t)((ks * 16 + kofA) * 2);
                const uint32_t kxB = (uint32_t)((ks * 16 + kofB) * 2);
                uint32_t ah[3][4], al[3][4];
                const uint32_t abase = sb + SM_A + kc * 2048 + (aBase ^ kxA);
                #pragma unroll
                for (int c = 0; c < 3; c++) {
                    ldsm4(ah[c], abase + c * 8192);
                    ldsm4(al[c], abase + (3 + c) * 8192);
                }
                #pragma unroll
                for (int r = 0; r < 2; r++)
                    #pragma unroll
                    for (int nf16 = 0; nf16 < 2; nf16++) {
                        uint32_t bh[4];
                        ldsm4(bh, wbase + (bBase[r][nf16] ^ kxB));
                        #pragma unroll
                        for (int c = 0; c < 3; c++) {
                            mma_fp16(acc[r][c][nf16 * 2],     ah[c], bh[0], bh[1]);
                            mma_fp16(acc[r][c][nf16 * 2],     al[c], bh[0], bh[1]);
                            mma_fp16(acc[r][c][nf16 * 2 + 1], ah[c], bh[2], bh[3]);
                            mma_fp16(acc[r][c][nf16 * 2 + 1], al[c], bh[2], bh[3]);
                        }
                    }
            }
        }
        __syncthreads();    // all A reads done before epilogue overwrites A

        if (layer == 0) {
            // tanh triple rule -> write next A planes (fp16 hi/lo, in place)
            #pragma unroll
            for (int r = 0; r < 2; r++) {
                int colb = cp * 64 + r * 32;
                #pragma unroll
                for (int nf = 0; nf < 4; nf++) {
                    int col = colb + nf * 8 + (lane & 3) * 2;
                    #pragma unroll
                    for (int half = 0; half < 2; half++) {
                        int row = r0 + half * 8;
                        uint32_t pk[6] = {0, 0, 0, 0, 0, 0};
                        #pragma unroll
                        for (int j = 0; j < 2; j++) {
                            float z  = acc[r][0][nf][half * 2 + j] + __ldg(&b2[col + j]);
                            float z1 = acc[r][1][nf][half * 2 + j];
                            float z2 = acc[r][2][nf][half * 2 + j];
                            float th = tanhf(z);
                            float u  = fmaf(-th, th, 1.0f);
                            float v0 = th, v1 = u * z1;
                            float v2 = fmaf(u, z2, -2.0f * th * v1 * z1);
                            uint32_t lo, hi;
                            hi = f2h(v0, lo); pk[0] |= hi << (16 * j); pk[3] |= lo << (16 * j);
                            hi = f2h(v1, lo); pk[1] |= hi << (16 * j); pk[4] |= lo << (16 * j);
                            hi = f2h(v2, lo); pk[2] |= hi << (16 * j); pk[5] |= lo << (16 * j);
                        }
                        uint32_t off = sb + SM_A + (col >> 6) * 2048 +
                                       sw128((uint32_t)(row * 128 + (col & 63) * 2));
                        #pragma unroll
                        for (int p = 0; p < 6; p++) sts32(off + p * 8192, pk[p]);
                    }
                }
            }
        } else {
            // tanh triple rule fused with layer-4 dot products (W4)
            #pragma unroll
            for (int r = 0; r < 2; r++) {
                int colb = cp * 64 + r * 32;
                #pragma unroll
                for (int nf = 0; nf < 4; nf++) {
                    int col = colb + nf * 8 + (lane & 3) * 2;
                    #pragma unroll
                    for (int half = 0; half < 2; half++) {
                        #pragma unroll
                        for (int j = 0; j < 2; j++) {
                            float z  = acc[r][0][nf][half * 2 + j] + __ldg(&b3[col + j]);
                            float z1 = acc[r][1][nf][half * 2 + j];
                            float z2 = acc[r][2][nf][half * 2 + j];
                            float th = tanhf(z);
                            float u  = fmaf(-th, th, 1.0f);
                            float v0 = th, v1 = u * z1;
                            float v2 = fmaf(u, z2, -2.0f * th * v1 * z1);
                            float w4v = __ldg(&W4[col + j]);
                            s4[half][0] = fmaf(v0, w4v, s4[half][0]);
                            s4[half][1] = fmaf(v1, w4v, s4[half][1]);
                            s4[half][2] = fmaf(v2, w4v, s4[half][2]);
                        }
                    }
                }
            }
        }
    }

    // ---------------- layer-4 reduction ----------------
    #pragma unroll
    for (int half = 0; half < 2; half++)
        #pragma unroll
        for (int c = 0; c < 3; c++) {
            float v = s4[half][c];
            v += __shfl_xor_sync(0xffffffffu, v, 1);
            v += __shfl_xor_sync(0xffffffffu, v, 2);
            s4[half][c] = v;
        }
    float* red = (float*)(smem + SM_RED);
    if ((lane & 3) == 0) {
        int q  = lane >> 2;              // 0..7
        int ra = q, rb = q + 8;
        #pragma unroll
        for (int c = 0; c < 3; c++) {
            red[c * 64 + ra * 4 + cp] = s4[0][c];
            red[c * 64 + rb * 4 + cp] = s4[1][c];
        }
    }
    __syncthreads();
    if (tid < 48) {
        int ch = tid >> 4, row = tid & 15;
        float s = red[ch * 64 + row * 4 + 0] + red[ch * 64 + row * 4 + 1] +
                  red[ch * 64 + row * 4 + 2] + red[ch * 64 + row * 4 + 3];
        if (ch == 0) s += b4[0];
        out[ch * Btot + gr0 + row] = s;
    }
}

extern "C" void kernel_launch(void* const* d_in, const int* in_sizes, int n_in,
                              void* d_out, int out_size)
{
    const float* x  = (const float*)d_in[0];
    const float* W1 = (const float*)d_in[1];
    const float* b1 = (const float*)d_in[2];
    const float* W2 = (const float*)d_in[3];
    const float* b2 = (const float*)d_in[4];
    const float* W3 = (const float*)d_in[5];
    const float* b3 = (const float*)d_in[6];
    const float* W4 = (const float*)d_in[7];
    const float* b4 = (const float*)d_in[8];
    float* out = (float*)d_out;

    int Btot = in_sizes[0] / 2;          // 131072
    int grid = Btot / MROWS;             // 8192 CTAs

    cudaFuncSetAttribute(pinn_tc_kernel,
                         cudaFuncAttributeMaxDynamicSharedMemorySize, SM_TOTAL);

    prep_kernel<<<512, 256>>>(W2, W3);
    pinn_tc_kernel<<<grid, THREADS, SM_TOTAL>>>(x, W1, b1, b2, b3, W4, b4, out, Btot);
}